// round 3
// baseline (speedup 1.0000x reference)
#include <cuda_runtime.h>
#include <math.h>

#define B_ 16
#define S_ 512
#define D_ 512
#define V_ 32000
#define K_ 4
#define T_ 64
#define SOS_ 1
#define EOS_ 2
#define PAD_ 0
#define NEGF (-1e9f)
#define NINF (-3.4e38f)

// ---------------- device scratch (no allocation allowed) ----------------
__device__ float g_encK[B_ * S_ * D_];        // 16.8 MB
__device__ float g_x[B_ * K_ * D_];           // e (+ctx)
__device__ float g_q[B_ * K_ * D_];
__device__ float g_logits[B_ * K_ * V_];      // 8.2 MB
__device__ float g_cand_lp[B_ * K_ * K_];
__device__ int   g_cand_v[B_ * K_ * K_];
__device__ float g_scores[B_ * K_];
__device__ int   g_finished[B_ * K_];
__device__ int   g_last[B_ * K_];
__device__ int   g_seqs[B_ * K_ * T_];

// ---------------- generic SGEMM: C[M,N] = A[M,K] * B[K,N] (+bias) ----------------
// Row-major everything. Tiles: 64x64, K-chunk 16, 256 threads, 4x4 micro-tile.
__global__ __launch_bounds__(256, 4) void gemm_rm(
    const float* __restrict__ A, const float* __restrict__ Bm,
    const float* __restrict__ bias, float* __restrict__ C,
    int M, int N, int Kd)
{
    __shared__ float As[16][64];
    __shared__ float Bs[16][64];
    int n0 = blockIdx.x * 64;
    int m0 = blockIdx.y * 64;
    int tid = threadIdx.x;
    int tm = tid >> 4;          // 0..15
    int tn = tid & 15;          // 0..15
    float acc[4][4] = {};
    for (int k0 = 0; k0 < Kd; k0 += 16) {
        #pragma unroll
        for (int i = 0; i < 4; i++) {
            int e = tid + i * 256;
            int m = e >> 4, kk = e & 15;
            As[kk][m] = A[(size_t)(m0 + m) * Kd + k0 + kk];
        }
        #pragma unroll
        for (int i = 0; i < 4; i++) {
            int e = tid + i * 256;
            int kk = e >> 6, n = e & 63;
            Bs[kk][n] = Bm[(size_t)(k0 + kk) * N + n0 + n];
        }
        __syncthreads();
        #pragma unroll
        for (int kk = 0; kk < 16; kk++) {
            float4 av = *(const float4*)&As[kk][tm * 4];
            float4 bv = *(const float4*)&Bs[kk][tn * 4];
            float a[4] = {av.x, av.y, av.z, av.w};
            float b[4] = {bv.x, bv.y, bv.z, bv.w};
            #pragma unroll
            for (int i = 0; i < 4; i++)
                #pragma unroll
                for (int j = 0; j < 4; j++)
                    acc[i][j] += a[i] * b[j];
        }
        __syncthreads();
    }
    #pragma unroll
    for (int i = 0; i < 4; i++) {
        int m = m0 + tm * 4 + i;
        #pragma unroll
        for (int j = 0; j < 4; j++) {
            int n = n0 + tn * 4 + j;
            float v = acc[i][j];
            if (bias) v += bias[n];
            C[(size_t)m * N + n] = v;
        }
    }
}

// ---------------- q = e @ W_q; also stash e into g_x ----------------
// mode==0: token = SOS for all rows; rows >= nactive are zero-filled (padding
// rows so the logits GEMM can always run M=64).
__global__ __launch_bounds__(256) void k_qe(
    const float* __restrict__ emb, const float* __restrict__ Wq,
    int mode, int nactive)
{
    int r = blockIdx.x;
    int tid = threadIdx.x;
    if (mode == 0 && r >= nactive) {
        for (int i = tid; i < D_; i += 256) { g_x[r * D_ + i] = 0.f; g_q[r * D_ + i] = 0.f; }
        return;
    }
    int tok = (mode == 0) ? SOS_ : g_last[r];
    __shared__ float e[D_];
    for (int i = tid; i < D_; i += 256) e[i] = emb[(size_t)tok * D_ + i];
    __syncthreads();
    int j0 = tid, j1 = tid + 256;
    float q0 = 0.f, q1 = 0.f;
    for (int d = 0; d < D_; d++) {
        float ed = e[d];
        q0 += ed * Wq[d * D_ + j0];
        q1 += ed * Wq[d * D_ + j1];
    }
    g_q[r * D_ + j0] = q0;
    g_q[r * D_ + j1] = q1;
    for (int i = tid; i < D_; i += 256) g_x[r * D_ + i] = e[i];
}

// ---------------- attention: att = softmax(q.encK masked), x += att @ enc ----------------
__global__ __launch_bounds__(256) void k_att(
    const float* __restrict__ enc, const int* __restrict__ lens, int mode)
{
    int r = blockIdx.x;
    int b = (mode == 0) ? r : (r >> 2);
    int tid = threadIdx.x, lane = tid & 31, w = tid >> 5;
    __shared__ float sq[D_];
    __shared__ float att[S_];
    __shared__ float red[256];
    for (int i = tid; i < D_; i += 256) sq[i] = g_q[r * D_ + i];
    __syncthreads();
    int len = lens[b];
    const float scale = 0.044194173824159216f;  // 1/sqrt(512)
    for (int s = w; s < S_; s += 8) {
        const float* kr = &g_encK[((size_t)b * S_ + s) * D_];
        float acc = 0.f;
        for (int d = lane; d < D_; d += 32) acc += sq[d] * kr[d];
        #pragma unroll
        for (int o = 16; o; o >>= 1) acc += __shfl_down_sync(0xffffffffu, acc, o);
        if (lane == 0) att[s] = (s < len) ? acc * scale : NEGF;
    }
    __syncthreads();
    // softmax over att[512]
    float m = NINF;
    for (int i = tid; i < S_; i += 256) m = fmaxf(m, att[i]);
    red[tid] = m; __syncthreads();
    for (int st = 128; st; st >>= 1) { if (tid < st) red[tid] = fmaxf(red[tid], red[tid + st]); __syncthreads(); }
    m = red[0]; __syncthreads();
    float loc = 0.f;
    for (int i = tid; i < S_; i += 256) { float p = expf(att[i] - m); att[i] = p; loc += p; }
    red[tid] = loc; __syncthreads();
    for (int st = 128; st; st >>= 1) { if (tid < st) red[tid] += red[tid + st]; __syncthreads(); }
    float inv = 1.f / red[0];
    __syncthreads();
    // ctx = (att/sum) @ enc[b]
    int d0 = tid, d1 = tid + 256;
    float c0 = 0.f, c1 = 0.f;
    const float* eb = &enc[(size_t)b * S_ * D_];
    for (int s = 0; s < S_; s++) {
        float p = att[s];
        c0 += p * eb[(size_t)s * D_ + d0];
        c1 += p * eb[(size_t)s * D_ + d1];
    }
    g_x[r * D_ + d0] += c0 * inv;
    g_x[r * D_ + d1] += c1 * inv;
}

// ---------------- per-row: top-4 of logits (stable) + logsumexp -> cand ----------------
__global__ __launch_bounds__(256) void k_reduce()
{
    int r = blockIdx.x;
    const float* L = &g_logits[(size_t)r * V_];
    int tid = threadIdx.x;
    __shared__ float rv[256];
    __shared__ int   ri[256];
    float topv[4]; int topi[4];
    int c0 = -1, c1 = -1, c2 = -1;
    for (int j = 0; j < 4; j++) {
        float bv = NINF; int bi = 0x7fffffff;
        for (int i = tid; i < V_; i += 256) {
            if (i == c0 || i == c1 || i == c2) continue;
            float v = L[i];
            if (v > bv || (v == bv && i < bi)) { bv = v; bi = i; }
        }
        rv[tid] = bv; ri[tid] = bi; __syncthreads();
        for (int st = 128; st; st >>= 1) {
            if (tid < st) {
                if (rv[tid + st] > rv[tid] ||
                    (rv[tid + st] == rv[tid] && ri[tid + st] < ri[tid])) {
                    rv[tid] = rv[tid + st]; ri[tid] = ri[tid + st];
                }
            }
            __syncthreads();
        }
        topv[j] = rv[0]; topi[j] = ri[0];
        __syncthreads();
        if (j == 0) c0 = topi[0];
        else if (j == 1) c1 = topi[1];
        else if (j == 2) c2 = topi[2];
    }
    // logsumexp with global max = topv[0]
    float s = 0.f;
    for (int i = tid; i < V_; i += 256) s += expf(L[i] - topv[0]);
    rv[tid] = s; __syncthreads();
    for (int st = 128; st; st >>= 1) { if (tid < st) rv[tid] += rv[tid + st]; __syncthreads(); }
    float lse = topv[0] + logf(rv[0]);
    if (tid < 4) {
        g_cand_lp[r * 4 + tid] = topv[tid] - lse;
        g_cand_v[r * 4 + tid] = topi[tid];
    }
}

// ---------------- step-1 init: expand SOS into top-K beams ----------------
__global__ void k_init()
{
    int tid = threadIdx.x;
    if (tid < B_ * K_) {
        int b = tid >> 2, k = tid & 3;
        float lp = g_cand_lp[b * 4 + k];   // reduce ran rows r = b
        int tok = g_cand_v[b * 4 + k];
        g_scores[tid] = lp;
        g_finished[tid] = (tok == EOS_) ? 1 : 0;
        g_last[tid] = tok;
        for (int i = 0; i < T_; i++) {
            int v = (i == 0) ? SOS_ : ((i == 1) ? tok : PAD_);
            g_seqs[tid * T_ + i] = v;
        }
    }
}

// ---------------- beam combine for step t ----------------
__global__ void k_beam(int t)
{
    int b = blockIdx.x;
    int tid = threadIdx.x;   // 32
    __shared__ float total[16];
    __shared__ int   cv[16];
    __shared__ float ns[4];
    __shared__ int   nidx[4];
    __shared__ int   sseq[4][T_];
    __shared__ float oscore[4];
    __shared__ int   ofin[4];
    if (tid < 4) { oscore[tid] = g_scores[b * 4 + tid]; ofin[tid] = g_finished[b * 4 + tid]; }
    __syncthreads();
    if (tid < 16) {
        int k = tid >> 2, j = tid & 3;
        float lp; int v;
        if (ofin[k]) { lp = (j == 0) ? 0.f : NEGF; v = PAD_; }
        else { lp = g_cand_lp[(b * 4 + k) * 4 + j]; v = g_cand_v[(b * 4 + k) * 4 + j]; }
        total[tid] = oscore[k] + lp;
        cv[tid] = v;
    }
    __syncthreads();
    if (tid == 0) {
        bool used[16] = {};
        for (int j = 0; j < 4; j++) {
            float bv = NINF; int bi = 0;
            bool found = false;
            for (int i = 0; i < 16; i++) {
                if (used[i]) continue;
                if (!found || total[i] > bv) { bv = total[i]; bi = i; found = true; }
            }
            used[bi] = true; ns[j] = bv; nidx[j] = bi;
        }
    }
    __syncthreads();
    for (int k = 0; k < 4; k++) {
        int src = nidx[k] >> 2;
        for (int i = tid; i < T_; i += 32) sseq[k][i] = g_seqs[(b * 4 + src) * T_ + i];
    }
    __syncthreads();
    for (int k = 0; k < 4; k++) {
        int tok = cv[nidx[k]];
        for (int i = tid; i < T_; i += 32) g_seqs[(b * 4 + k) * T_ + i] = (i == t) ? tok : sseq[k][i];
    }
    if (tid < 4) {
        int k = tid;
        int src = nidx[k] >> 2;
        int tok = cv[nidx[k]];
        g_scores[b * 4 + k] = ns[k];
        g_finished[b * 4 + k] = ofin[src] | ((tok == EOS_) ? 1 : 0);
        g_last[b * 4 + k] = tok;
    }
}

// ---------------- final: argmax beam, write output ----------------
__global__ void k_final(float* __restrict__ out, int out_size)
{
    int b = blockIdx.x;
    int tid = threadIdx.x;   // 64
    __shared__ int best;
    if (tid == 0) {
        float bv = NINF; int bi = 0;
        for (int k = 0; k < 4; k++) {
            float v = g_scores[b * 4 + k];
            if (v > bv) { bv = v; bi = k; }
        }
        best = bi;
        if (out_size >= B_ * T_ + B_) out[B_ * T_ + b] = bv;
    }
    __syncthreads();
    int oidx = b * T_ + tid;
    if (oidx < out_size) out[oidx] = (float)g_seqs[(b * 4 + best) * T_ + tid];
}

// ---------------- host orchestration ----------------
extern "C" void kernel_launch(void* const* d_in, const int* in_sizes, int n_in,
                              void* d_out, int out_size)
{
    const float* enc  = (const float*)d_in[0];   // [16,512,512]
    const int*   lens = (const int*)d_in[1];     // [16]
    const float* emb  = (const float*)d_in[2];   // [32000,512]
    const float* Wq   = (const float*)d_in[3];   // [512,512]
    const float* Wk   = (const float*)d_in[4];   // [512,512]
    const float* Wfc  = (const float*)d_in[5];   // [512,32000]
    const float* bfc  = (const float*)d_in[6];   // [32000]
    float* out = (float*)d_out;

    float *p_encK, *p_x, *p_logits;
    cudaGetSymbolAddress((void**)&p_encK, g_encK);
    cudaGetSymbolAddress((void**)&p_x, g_x);
    cudaGetSymbolAddress((void**)&p_logits, g_logits);

    // encK = enc @ W_k  : M=8192, N=512, K=512
    {
        dim3 grid(D_ / 64, (B_ * S_) / 64);
        gemm_rm<<<grid, 256>>>(enc, Wk, nullptr, p_encK, B_ * S_, D_, D_);
    }

    // ---- step 1: expand SOS ----
    k_qe<<<B_ * K_, 256>>>(emb, Wq, 0, B_);
    k_att<<<B_, 256>>>(enc, lens, 0);
    {
        dim3 grid(V_ / 64, 1);
        gemm_rm<<<grid, 256>>>(p_x, Wfc, bfc, p_logits, B_ * K_, V_, D_);
    }
    k_reduce<<<B_, 256>>>();
    k_init<<<1, 64>>>();

    // ---- steps t = 2..63 ----
    for (int t = 2; t < T_; t++) {
        k_qe<<<B_ * K_, 256>>>(emb, Wq, 1, B_ * K_);
        k_att<<<B_ * K_, 256>>>(enc, lens, 1);
        dim3 grid(V_ / 64, 1);
        gemm_rm<<<grid, 256>>>(p_x, Wfc, bfc, p_logits, B_ * K_, V_, D_);
        k_reduce<<<B_ * K_, 256>>>();
        k_beam<<<B_, 32>>>(t);
    }

    k_final<<<B_, 64>>>(out, out_size);
}

// round 4
// speedup vs baseline: 1.1870x; 1.1870x over previous
#include <cuda_runtime.h>
#include <math.h>
#include <stdint.h>

#define B_ 16
#define S_ 512
#define D_ 512
#define V_ 32000
#define K_ 4
#define T_ 64
#define SOS_ 1
#define EOS_ 2
#define PAD_ 0
#define NEGF (-1e9f)
#define NINF (-3.4e38f)

// ---------------- device scratch ----------------
__device__ float g_encK[B_ * S_ * D_];        // 16.8 MB
__device__ float g_x[64 * D_];                // e + ctx (64 rows, padded)
__device__ float g_logits[64 * V_];           // 8.2 MB
__device__ float g_scores[B_ * K_];
__device__ int   g_finished[B_ * K_];
__device__ int   g_last[B_ * K_];
__device__ int   g_seqs[B_ * K_ * T_];
// per-(row, chunk) partial top4 + lse pieces: 64 rows x 4 chunks
__device__ float g_pv[64 * 4 * 4];
__device__ int   g_pi[64 * 4 * 4];
__device__ float g_pm[64 * 4];
__device__ float g_ps[64 * 4];

// ---------------- cp.async helpers ----------------
__device__ __forceinline__ unsigned smem_u32p(const void* p) {
    return (unsigned)__cvta_generic_to_shared(p);
}
#define CPA4(dst, src)  asm volatile("cp.async.ca.shared.global [%0], [%1], 4;"  :: "r"(dst), "l"(src))
#define CPA16(dst, src) asm volatile("cp.async.cg.shared.global [%0], [%1], 16;" :: "r"(dst), "l"(src))
#define CPCOMMIT()      asm volatile("cp.async.commit_group;")
#define CPWAIT0()       asm volatile("cp.async.wait_group 0;")
#define CPWAIT1()       asm volatile("cp.async.wait_group 1;")

// ---------------- GEMM v2: C[M,N] = A[M,K] @ B[K,N] (+bias) ----------------
// 64x64 tile, KC=32, double-buffered cp.async, 256 threads, 4x4 micro-tile.
#define KC 32
__global__ __launch_bounds__(256) void gemm_v2(
    const float* __restrict__ A, const float* __restrict__ Bm,
    const float* __restrict__ bias, float* __restrict__ C,
    int N, int Kd)
{
    __shared__ float As[2][KC][65];   // pad 65: conflict-free k-major stores
    __shared__ float Bs[2][KC][64];
    int n0 = blockIdx.x * 64;
    int m0 = blockIdx.y * 64;
    int tid = threadIdx.x;
    int tm = tid >> 4;          // 0..15
    int tn = tid & 15;          // 0..15

    // A-load mapping: coalesced along K
    int a_m = tid >> 5;         // 0..7
    int a_k = tid & 31;         // 0..31
    // B-load mapping: one float4 per (thread, kk2)
    int b_k = tid >> 4;         // 0..15
    int b_n = (tid & 15) * 4;

    float acc[4][4] = {};
    const int NT = Kd / KC;

    // prefetch chunk 0
    {
        const float* Ag = A + (size_t)(m0 + a_m) * Kd + a_k;
        #pragma unroll
        for (int mm = 0; mm < 64; mm += 8)
            CPA4(smem_u32p(&As[0][a_k][a_m + mm]), Ag + (size_t)mm * Kd);
        #pragma unroll
        for (int kk2 = 0; kk2 < 2; kk2++) {
            int kk = b_k + kk2 * 16;
            CPA16(smem_u32p(&Bs[0][kk][b_n]), Bm + (size_t)kk * N + n0 + b_n);
        }
        CPCOMMIT();
    }

    for (int kt = 0; kt < NT; kt++) {
        int buf = kt & 1;
        if (kt + 1 < NT) {
            int k0 = (kt + 1) * KC;
            const float* Ag = A + (size_t)(m0 + a_m) * Kd + k0 + a_k;
            #pragma unroll
            for (int mm = 0; mm < 64; mm += 8)
                CPA4(smem_u32p(&As[buf ^ 1][a_k][a_m + mm]), Ag + (size_t)mm * Kd);
            #pragma unroll
            for (int kk2 = 0; kk2 < 2; kk2++) {
                int kk = b_k + kk2 * 16;
                CPA16(smem_u32p(&Bs[buf ^ 1][kk][b_n]), Bm + (size_t)(k0 + kk) * N + n0 + b_n);
            }
            CPCOMMIT();
            CPWAIT1();
        } else {
            CPWAIT0();
        }
        __syncthreads();
        #pragma unroll
        for (int kk = 0; kk < KC; kk++) {
            float a0 = As[buf][kk][tm * 4 + 0];
            float a1 = As[buf][kk][tm * 4 + 1];
            float a2 = As[buf][kk][tm * 4 + 2];
            float a3 = As[buf][kk][tm * 4 + 3];
            float4 bv = *(const float4*)&Bs[buf][kk][tn * 4];
            acc[0][0] += a0 * bv.x; acc[0][1] += a0 * bv.y; acc[0][2] += a0 * bv.z; acc[0][3] += a0 * bv.w;
            acc[1][0] += a1 * bv.x; acc[1][1] += a1 * bv.y; acc[1][2] += a1 * bv.z; acc[1][3] += a1 * bv.w;
            acc[2][0] += a2 * bv.x; acc[2][1] += a2 * bv.y; acc[2][2] += a2 * bv.z; acc[2][3] += a2 * bv.w;
            acc[3][0] += a3 * bv.x; acc[3][1] += a3 * bv.y; acc[3][2] += a3 * bv.z; acc[3][3] += a3 * bv.w;
        }
        __syncthreads();
    }
    #pragma unroll
    for (int i = 0; i < 4; i++) {
        int m = m0 + tm * 4 + i;
        #pragma unroll
        for (int j = 0; j < 4; j++) {
            int n = n0 + tn * 4 + j;
            float v = acc[i][j];
            if (bias) v += bias[n];
            C[(size_t)m * N + n] = v;
        }
    }
}

// ---------------- fused: e = emb[tok]; q = e@Wq; att softmax; x = e + ctx ----------------
__global__ __launch_bounds__(256) void k_qeatt(
    const float* __restrict__ emb, const float* __restrict__ Wq,
    const float* __restrict__ enc, const int* __restrict__ lens, int mode)
{
    int r = blockIdx.x;
    int tid = threadIdx.x, lane = tid & 31, w = tid >> 5;
    if (mode == 0 && r >= B_) {
        for (int i = tid; i < D_; i += 256) g_x[r * D_ + i] = 0.f;
        return;
    }
    int tok = mode ? g_last[r] : SOS_;
    int b = mode ? (r >> 2) : r;
    __shared__ float e[D_];
    __shared__ float sq[D_];
    __shared__ float att[S_];
    __shared__ float red[256];
    for (int i = tid; i < D_; i += 256) e[i] = emb[(size_t)tok * D_ + i];
    __syncthreads();
    // q = e @ Wq  (each thread 2 output cols, 2-way k-unroll)
    {
        int j0 = tid, j1 = tid + 256;
        float q0 = 0.f, q1 = 0.f, q2 = 0.f, q3 = 0.f;
        for (int d = 0; d < D_; d += 2) {
            float e0 = e[d], e1 = e[d + 1];
            q0 += e0 * Wq[d * D_ + j0];
            q1 += e0 * Wq[d * D_ + j1];
            q2 += e1 * Wq[(d + 1) * D_ + j0];
            q3 += e1 * Wq[(d + 1) * D_ + j1];
        }
        sq[j0] = q0 + q2;
        sq[j1] = q1 + q3;
    }
    __syncthreads();
    int len = lens[b];
    const float scale = 0.044194173824159216f;  // 1/sqrt(512)
    for (int s = w; s < S_; s += 8) {
        const float* kr = &g_encK[((size_t)b * S_ + s) * D_];
        float a0 = 0.f, a1 = 0.f, a2 = 0.f, a3 = 0.f;
        for (int d = lane; d < D_; d += 128) {
            a0 += sq[d] * kr[d];
            a1 += sq[d + 32] * kr[d + 32];
            a2 += sq[d + 64] * kr[d + 64];
            a3 += sq[d + 96] * kr[d + 96];
        }
        float acc = (a0 + a1) + (a2 + a3);
        #pragma unroll
        for (int o = 16; o; o >>= 1) acc += __shfl_down_sync(0xffffffffu, acc, o);
        if (lane == 0) att[s] = (s < len) ? acc * scale : NEGF;
    }
    __syncthreads();
    // softmax over att[512]
    float m = NINF;
    for (int i = tid; i < S_; i += 256) m = fmaxf(m, att[i]);
    red[tid] = m; __syncthreads();
    for (int st = 128; st; st >>= 1) { if (tid < st) red[tid] = fmaxf(red[tid], red[tid + st]); __syncthreads(); }
    m = red[0]; __syncthreads();
    float loc = 0.f;
    for (int i = tid; i < S_; i += 256) { float p = expf(att[i] - m); att[i] = p; loc += p; }
    red[tid] = loc; __syncthreads();
    for (int st = 128; st; st >>= 1) { if (tid < st) red[tid] += red[tid + st]; __syncthreads(); }
    float inv = 1.f / red[0];
    __syncthreads();
    // x = e + (att/sum) @ enc[b]
    {
        int d0 = tid, d1 = tid + 256;
        float c0 = 0.f, c1 = 0.f, c2 = 0.f, c3 = 0.f;
        const float* eb = &enc[(size_t)b * S_ * D_];
        for (int s = 0; s < S_; s += 2) {
            float p0 = att[s], p1 = att[s + 1];
            c0 += p0 * eb[(size_t)s * D_ + d0];
            c1 += p0 * eb[(size_t)s * D_ + d1];
            c2 += p1 * eb[(size_t)(s + 1) * D_ + d0];
            c3 += p1 * eb[(size_t)(s + 1) * D_ + d1];
        }
        g_x[r * D_ + d0] = e[d0] + (c0 + c2) * inv;
        g_x[r * D_ + d1] = e[d1] + (c1 + c3) * inv;
    }
}

// ---------------- stable merge of two top4 lists (value desc, index asc) ----------------
__device__ __forceinline__ void merge4(float* av, int* ai, const float* bv, const int* bi)
{
    float rv[4]; int ri[4];
    int ia = 0, ib = 0;
    #pragma unroll
    for (int q = 0; q < 4; q++) {
        float va = av[ia], vb = bv[ib];
        int xa = ai[ia], xb = bi[ib];
        bool ta = (va > vb) || (va == vb && xa < xb);
        rv[q] = ta ? va : vb;
        ri[q] = ta ? xa : xb;
        if (ta) ia++; else ib++;
    }
    #pragma unroll
    for (int q = 0; q < 4; q++) { av[q] = rv[q]; ai[q] = ri[q]; }
}

// ---------------- single-pass partial top4 + online lse per (row, chunk) ----------------
// grid: (4 chunks, 64 rows), 256 threads
__global__ __launch_bounds__(256) void k_topk_part()
{
    int c = blockIdx.x, r = blockIdx.y;
    const float* L = &g_logits[(size_t)r * V_];
    int tid = threadIdx.x;
    int i0 = c * (V_ / 4), i1 = i0 + (V_ / 4);
    float tv[4] = {NINF, NINF, NINF, NINF};
    int   ti[4] = {0x7fffffff, 0x7fffffff, 0x7fffffff, 0x7fffffff};
    float m = NINF, s = 0.f;
    for (int i = i0 + tid; i < i1; i += 256) {
        float v = L[i];
        if (v > m) { s = s * expf(m - v) + 1.f; m = v; }
        else       { s += expf(v - m); }
        if (v > tv[3]) {
            tv[3] = v; ti[3] = i;
            #pragma unroll
            for (int p = 3; p > 0; p--) {
                if (tv[p] > tv[p - 1]) {
                    float tf = tv[p]; tv[p] = tv[p - 1]; tv[p - 1] = tf;
                    int tt = ti[p]; ti[p] = ti[p - 1]; ti[p - 1] = tt;
                }
            }
        }
    }
    __shared__ float sv[256][4];
    __shared__ int   si[256][4];
    __shared__ float smx[256], ssm[256];
    #pragma unroll
    for (int j = 0; j < 4; j++) { sv[tid][j] = tv[j]; si[tid][j] = ti[j]; }
    smx[tid] = m; ssm[tid] = s;
    __syncthreads();
    for (int st = 128; st; st >>= 1) {
        if (tid < st) {
            merge4(&sv[tid][0], &si[tid][0], &sv[tid + st][0], &si[tid + st][0]);
            float ma = smx[tid], mb = smx[tid + st];
            float mm = fmaxf(ma, mb);
            ssm[tid] = ssm[tid] * expf(ma - mm) + ssm[tid + st] * expf(mb - mm);
            smx[tid] = mm;
        }
        __syncthreads();
    }
    if (tid == 0) {
        int pc = r * 4 + c;
        #pragma unroll
        for (int j = 0; j < 4; j++) { g_pv[pc * 4 + j] = sv[0][j]; g_pi[pc * 4 + j] = si[0][j]; }
        g_pm[pc] = smx[0];
        g_ps[pc] = ssm[0];
    }
}

// ---------------- merge 4 chunk-partials of a row -> top4 + lse ----------------
__device__ __forceinline__ void merge_row(int r, float* tv, int* ti, float& lse)
{
    int p0 = r * 4;
    float m = g_pm[p0], s = g_ps[p0];
    #pragma unroll
    for (int j = 0; j < 4; j++) { tv[j] = g_pv[p0 * 4 + j]; ti[j] = g_pi[p0 * 4 + j]; }
    for (int c = 1; c < 4; c++) {
        float bv[4]; int bi_[4];
        #pragma unroll
        for (int j = 0; j < 4; j++) { bv[j] = g_pv[(p0 + c) * 4 + j]; bi_[j] = g_pi[(p0 + c) * 4 + j]; }
        merge4(tv, ti, bv, bi_);
        float mb = g_pm[p0 + c], sb = g_ps[p0 + c];
        float mm = fmaxf(m, mb);
        s = s * expf(m - mm) + sb * expf(mb - mm);
        m = mm;
    }
    lse = m + logf(s);
}

// ---------------- step-1 init: expand SOS into top-K beams ----------------
__global__ void k_init()
{
    int b = threadIdx.x;
    if (b >= B_) return;
    float tv[4]; int ti[4]; float lse;
    merge_row(b, tv, ti, lse);   // step-1 logits are in rows r = b
    for (int k = 0; k < K_; k++) {
        int tok = ti[k];
        int r = b * K_ + k;
        g_scores[r] = tv[k] - lse;
        g_finished[r] = (tok == EOS_) ? 1 : 0;
        g_last[r] = tok;
        for (int i = 0; i < T_; i++)
            g_seqs[r * T_ + i] = (i == 0) ? SOS_ : ((i == 1) ? tok : PAD_);
    }
}

// ---------------- beam combine for step t (merges partials inline) ----------------
__global__ void k_beam(int t)
{
    int b = blockIdx.x;
    int tid = threadIdx.x;   // 32
    __shared__ float cand_lp[K_][K_];
    __shared__ int   cand_v[K_][K_];
    __shared__ float total[16];
    __shared__ int   cv[16];
    __shared__ float ns[4];
    __shared__ int   nidx[4];
    __shared__ int   sseq[4][T_];
    __shared__ float oscore[4];
    __shared__ int   ofin[4];
    if (tid < 4) {
        oscore[tid] = g_scores[b * 4 + tid];
        ofin[tid] = g_finished[b * 4 + tid];
        float tv[4]; int ti[4]; float lse;
        merge_row(b * 4 + tid, tv, ti, lse);
        #pragma unroll
        for (int j = 0; j < 4; j++) { cand_lp[tid][j] = tv[j] - lse; cand_v[tid][j] = ti[j]; }
    }
    __syncthreads();
    if (tid < 16) {
        int k = tid >> 2, j = tid & 3;
        float lp; int v;
        if (ofin[k]) { lp = (j == 0) ? 0.f : NEGF; v = PAD_; }
        else { lp = cand_lp[k][j]; v = cand_v[k][j]; }
        total[tid] = oscore[k] + lp;
        cv[tid] = v;
    }
    __syncthreads();
    if (tid == 0) {
        bool used[16] = {};
        for (int j = 0; j < 4; j++) {
            float bv = NINF; int bi = 0;
            bool found = false;
            for (int i = 0; i < 16; i++) {
                if (used[i]) continue;
                if (!found || total[i] > bv) { bv = total[i]; bi = i; found = true; }
            }
            used[bi] = true; ns[j] = bv; nidx[j] = bi;
        }
    }
    __syncthreads();
    for (int k = 0; k < 4; k++) {
        int src = nidx[k] >> 2;
        for (int i = tid; i < T_; i += 32) sseq[k][i] = g_seqs[(b * 4 + src) * T_ + i];
    }
    __syncthreads();
    for (int k = 0; k < 4; k++) {
        int tok = cv[nidx[k]];
        for (int i = tid; i < T_; i += 32) g_seqs[(b * 4 + k) * T_ + i] = (i == t) ? tok : sseq[k][i];
    }
    if (tid < 4) {
        int k = tid;
        int src = nidx[k] >> 2;
        int tok = cv[nidx[k]];
        g_scores[b * 4 + k] = ns[k];
        g_finished[b * 4 + k] = ofin[src] | ((tok == EOS_) ? 1 : 0);
        g_last[b * 4 + k] = tok;
    }
}

// ---------------- final: argmax beam, write output ----------------
__global__ void k_final(float* __restrict__ out, int out_size)
{
    int b = blockIdx.x;
    int tid = threadIdx.x;   // 64
    __shared__ int best;
    if (tid == 0) {
        float bv = NINF; int bi = 0;
        for (int k = 0; k < 4; k++) {
            float v = g_scores[b * 4 + k];
            if (v > bv) { bv = v; bi = k; }
        }
        best = bi;
        if (out_size >= B_ * T_ + B_) out[B_ * T_ + b] = bv;
    }
    __syncthreads();
    int oidx = b * T_ + tid;
    if (oidx < out_size) out[oidx] = (float)g_seqs[(b * 4 + best) * T_ + tid];
}

// ---------------- host orchestration ----------------
extern "C" void kernel_launch(void* const* d_in, const int* in_sizes, int n_in,
                              void* d_out, int out_size)
{
    const float* enc  = (const float*)d_in[0];   // [16,512,512]
    const int*   lens = (const int*)d_in[1];     // [16]
    const float* emb  = (const float*)d_in[2];   // [32000,512]
    const float* Wq   = (const float*)d_in[3];   // [512,512]
    const float* Wk   = (const float*)d_in[4];   // [512,512]
    const float* Wfc  = (const float*)d_in[5];   // [512,32000]
    const float* bfc  = (const float*)d_in[6];   // [32000]
    float* out = (float*)d_out;

    float *p_encK, *p_x, *p_logits;
    cudaGetSymbolAddress((void**)&p_encK, g_encK);
    cudaGetSymbolAddress((void**)&p_x, g_x);
    cudaGetSymbolAddress((void**)&p_logits, g_logits);

    // encK = enc @ W_k : M=8192, N=512, K=512
    gemm_v2<<<dim3(D_ / 64, (B_ * S_) / 64), 256>>>(enc, Wk, nullptr, p_encK, D_, D_);

    // ---- step 1 ----
    k_qeatt<<<64, 256>>>(emb, Wq, enc, lens, 0);
    gemm_v2<<<dim3(V_ / 64, 1), 256>>>(p_x, Wfc, bfc, p_logits, V_, D_);
    k_topk_part<<<dim3(4, 64), 256>>>();
    k_init<<<1, 16>>>();

    // ---- steps t = 2..63 ----
    for (int t = 2; t < T_; t++) {
        k_qeatt<<<64, 256>>>(emb, Wq, enc, lens, 1);
        gemm_v2<<<dim3(V_ / 64, 1), 256>>>(p_x, Wfc, bfc, p_logits, V_, D_);
        k_topk_part<<<dim3(4, 64), 256>>>();
        k_beam<<<B_, 32>>>(t);
    }

    k_final<<<B_, 64>>>(out, out_size);
}